// round 8
// baseline (speedup 1.0000x reference)
#include <cuda_runtime.h>
#include <cstdint>

#define NEG_INF -1e30f
#define QK_SCALE 0.08838834764831845f

constexpr int BS    = 16;    // keys per KV block
constexpr int D     = 128;   // head dim
constexpr int G     = 4;     // query heads per kv head
constexpr int HKV   = 8;
constexpr int HQ    = 32;
constexpr int BMAX  = 128;   // max KV blocks per sequence
constexpr int SMAX  = 32;    // sequences (dataset-fixed)
constexpr int WARPS = 4;
constexpr int THREADS = WARPS * 32;
constexpr int BPW   = 2;                   // KV blocks per warp
constexpr int CHUNK = WARPS * BPW;         // 8 KV blocks per CTA
constexpr int MAXCH = BMAX / CHUNK;        // 16 chunks max per (s,h)

// Split-K partial scratch (8MB acc + stats) + completion counters
__device__ float g_pm  [SMAX * HKV * MAXCH * G];
__device__ float g_pl  [SMAX * HKV * MAXCH * G];
__device__ float g_pacc[SMAX * HKV * MAXCH * G * D];
__device__ unsigned int g_cnt[SMAX * HKV];   // zero-initialized; reset by reducer

__launch_bounds__(THREADS, 6)
__global__ void paged_attn_split_kernel(const float* __restrict__ q,
                                        const float* __restrict__ kc,
                                        const float* __restrict__ vc,
                                        const int*   __restrict__ bt,
                                        const int*   __restrict__ sl,
                                        const float* __restrict__ slopes,
                                        const int*   __restrict__ qsl,
                                        float*       __restrict__ out)
{
    const int h    = blockIdx.x;   // kv head
    const int s    = blockIdx.y;   // sequence
    const int c    = blockIdx.z;   // KV chunk index
    const int tid  = threadIdx.x;
    const int w    = tid >> 5;
    const int lane = tid & 31;
    const int gp   = lane >> 4;
    const int j    = lane & 15;    // key within KV block (QK phase)

    const int q0   = qsl[s];
    const int qlen = qsl[s + 1] - q0;
    if (qlen != 1) {
        // non-decode rows are zero; chunk 0 writes them
        if (c == 0) {
#pragma unroll
            for (int g = 0; g < G; g++)
                out[((size_t)q0 * HQ + h * G + g) * D + tid] = 0.0f;
        }
        return;
    }
    const int seqlen = sl[s];
    const int nb = (seqlen + BS - 1) / BS;
    const int nch = (nb + CHUNK - 1) / CHUNK;
    if (c >= nch) return;

    __shared__ __align__(16) float sq[G][D];
    __shared__ __align__(16) float sp[WARPS][G][2 * BS];
    __shared__ float pm[WARPS][G];
    __shared__ float pl[WARPS][G];
    __shared__ float pacc[WARPS][G][D];
    __shared__ int s_last;

    for (int i = tid; i < G * D; i += THREADS)
        sq[0][i] = q[((size_t)q0 * HQ + h * G) * D + i];
    __syncthreads();

    const int bi0 = c * CHUNK + w * BPW;   // this warp's first KV block
    const int bi1 = bi0 + 1;
    const int ga = 2 * gp, gbh = ga + 1;

    if (bi0 < nb) {
        const int b0 = bt[s * BMAX + bi0];
        const int b1 = bt[s * BMAX + (bi1 < nb ? bi1 : bi0)];  // clamp: p==0 anyway
        const float* kb0 = kc + ((size_t)b0 * HKV + h) * 2048;
        const float* kb1 = kc + ((size_t)b1 * HKV + h) * 2048;

        // ---- QK^T for two blocks, interleaved loads ----
        float sA0 = 0.f, sA1 = 0.f, sB0 = 0.f, sB1 = 0.f;
#pragma unroll
        for (int dg = 0; dg < 16; dg++) {
            const float4 ka0 = *(const float4*)(kb0 + dg * 128 + j * 8);
            const float4 ka1 = *(const float4*)(kb0 + dg * 128 + j * 8 + 4);
            const float4 kc0 = *(const float4*)(kb1 + dg * 128 + j * 8);
            const float4 kc1 = *(const float4*)(kb1 + dg * 128 + j * 8 + 4);
            const float4 qa0 = *(const float4*)(&sq[ga][dg * 8]);
            const float4 qa1 = *(const float4*)(&sq[ga][dg * 8 + 4]);
            const float4 qb0 = *(const float4*)(&sq[gbh][dg * 8]);
            const float4 qb1 = *(const float4*)(&sq[gbh][dg * 8 + 4]);
            sA0 += ka0.x*qa0.x + ka0.y*qa0.y + ka0.z*qa0.z + ka0.w*qa0.w
                 + ka1.x*qa1.x + ka1.y*qa1.y + ka1.z*qa1.z + ka1.w*qa1.w;
            sA1 += ka0.x*qb0.x + ka0.y*qb0.y + ka0.z*qb0.z + ka0.w*qb0.w
                 + ka1.x*qb1.x + ka1.y*qb1.y + ka1.z*qb1.z + ka1.w*qb1.w;
            sB0 += kc0.x*qa0.x + kc0.y*qa0.y + kc0.z*qa0.z + kc0.w*qa0.w
                 + kc1.x*qa1.x + kc1.y*qa1.y + kc1.z*qa1.z + kc1.w*qa1.w;
            sB1 += kc0.x*qb0.x + kc0.y*qb0.y + kc0.z*qb0.z + kc0.w*qb0.w
                 + kc1.x*qb1.x + kc1.y*qb1.y + kc1.z*qb1.z + kc1.w*qb1.w;
        }
        const float ctx = (float)(seqlen - 1);
        const float sla = slopes[h * G + ga];
        const float slb = slopes[h * G + gbh];
        const int kposA = bi0 * BS + j;
        const int kposB = bi1 * BS + j;
        sA0 = sA0 * QK_SCALE + sla * ((float)kposA - ctx);
        sA1 = sA1 * QK_SCALE + slb * ((float)kposA - ctx);
        sB0 = sB0 * QK_SCALE + sla * ((float)kposB - ctx);
        sB1 = sB1 * QK_SCALE + slb * ((float)kposB - ctx);
        if (kposA >= seqlen) { sA0 = NEG_INF; sA1 = NEG_INF; }
        if (kposB >= seqlen) { sB0 = NEG_INF; sB1 = NEG_INF; }

        // ---- shared softmax over 32 keys (pair pre-max, one shuffle tree) ----
        float mb0 = fmaxf(sA0, sB0), mb1 = fmaxf(sA1, sB1);
#pragma unroll
        for (int o = 8; o; o >>= 1) {
            mb0 = fmaxf(mb0, __shfl_xor_sync(0xffffffffu, mb0, o));
            mb1 = fmaxf(mb1, __shfl_xor_sync(0xffffffffu, mb1, o));
        }
        const float pA0 = __expf(sA0 - mb0);
        const float pA1 = __expf(sA1 - mb1);
        const float pB0 = __expf(sB0 - mb0);
        const float pB1 = __expf(sB1 - mb1);
        float lb0 = pA0 + pB0, lb1 = pA1 + pB1;
#pragma unroll
        for (int o = 8; o; o >>= 1) {
            lb0 += __shfl_xor_sync(0xffffffffu, lb0, o);
            lb1 += __shfl_xor_sync(0xffffffffu, lb1, o);
        }

        sp[w][ga][j]        = pA0;
        sp[w][gbh][j]       = pA1;
        sp[w][ga][BS + j]   = pB0;
        sp[w][gbh][BS + j]  = pB1;
        if (j == 0) {
            pm[w][ga] = mb0;  pm[w][gbh] = mb1;
            pl[w][ga] = lb0;  pl[w][gbh] = lb1;
        }
        __syncwarp();

        // ---- PV, coalesced: lane l reads flat float4 (i*32+l) of V block ----
        const int kg = lane & 3;
        const int b0v = lane & 1;
        const int b1v = (lane >> 1) & 1;

        float4 pw0[G], pw1[G];
#pragma unroll
        for (int g = 0; g < G; g++) {
            pw0[g] = *(const float4*)(&sp[w][g][4 * kg]);
            pw1[g] = *(const float4*)(&sp[w][g][BS + 4 * kg]);
        }

        const float* vb0 = vc + ((size_t)b0 * HKV + h) * 2048;
        const float* vb1 = vc + ((size_t)b1 * HKV + h) * 2048;

        float acc[16];
#pragma unroll
        for (int i = 0; i < 16; i++) {
            const float4 vA = *(const float4*)(vb0 + (i * 32 + lane) * 4);
            const float4 vB = *(const float4*)(vb1 + (i * 32 + lane) * 4);
            float cg[G];
#pragma unroll
            for (int g = 0; g < G; g++) {
                cg[g] = vA.x*pw0[g].x + vA.y*pw0[g].y + vA.z*pw0[g].z + vA.w*pw0[g].w
                      + vB.x*pw1[g].x + vB.y*pw1[g].y + vB.z*pw1[g].z + vB.w*pw1[g].w;
            }
            const float s0 = cg[b0v]     + __shfl_xor_sync(0xffffffffu, cg[1 - b0v], 1);
            const float s1 = cg[2 + b0v] + __shfl_xor_sync(0xffffffffu, cg[3 - b0v], 1);
            const float keep = b1v ? s1 : s0;
            const float send = b1v ? s0 : s1;
            acc[i] = keep + __shfl_xor_sync(0xffffffffu, send, 2);
        }
        const int dr = lane >> 2;
#pragma unroll
        for (int i = 0; i < 16; i++)
            pacc[w][kg][8 * i + dr] = acc[i];
    } else {
        if (j == 0) {
            pm[w][ga] = NEG_INF;  pm[w][gbh] = NEG_INF;
            pl[w][ga] = 0.f;      pl[w][gbh] = 0.f;
        }
#pragma unroll
        for (int g = 0; g < G; g++)
#pragma unroll
            for (int dd = 0; dd < 4; dd++) pacc[w][g][4 * lane + dd] = 0.f;
    }
    __syncthreads();

    // ---- CTA merge over 4 warps -> one chunk partial ----
    const int d = tid;   // 128 threads, one output dim each
    const size_t base = (((size_t)s * HKV + h) * MAXCH + c) * G;
#pragma unroll
    for (int g = 0; g < G; g++) {
        float M = NEG_INF;
#pragma unroll
        for (int ww = 0; ww < WARPS; ww++) M = fmaxf(M, pm[ww][g]);
        float L = 0.f, num = 0.f;
#pragma unroll
        for (int ww = 0; ww < WARPS; ww++) {
            const float mw = pm[ww][g];
            const float f = (mw <= -1e29f) ? 0.f : __expf(mw - M);
            L   += f * pl[ww][g];
            num += f * pacc[ww][g][d];
        }
        g_pacc[(base + g) * D + d] = num;
        if (d == 0) { g_pm[base + g] = M; g_pl[base + g] = L; }
    }

    // ---- last CTA for this (s,h) merges all chunks and writes out ----
    __threadfence();
    __syncthreads();
    if (tid == 0) {
        const unsigned int ticket = atomicAdd(&g_cnt[s * HKV + h], 1u);
        s_last = (ticket == (unsigned int)(nch - 1));
    }
    __syncthreads();
    if (!s_last) return;
    __threadfence();   // acquire: make other CTAs' partials visible

    const size_t sbase = (((size_t)s * HKV + h) * MAXCH) * G;
#pragma unroll
    for (int g = 0; g < G; g++) {
        float M = NEG_INF;
#pragma unroll 4
        for (int cc = 0; cc < nch; cc++)
            M = fmaxf(M, g_pm[sbase + (size_t)cc * G + g]);
        float L = 0.f, num = 0.f;
#pragma unroll 4
        for (int cc = 0; cc < nch; cc++) {
            const float mw = g_pm[sbase + (size_t)cc * G + g];
            const float f = (mw <= -1e29f) ? 0.f : __expf(mw - M);
            L   += f * g_pl[sbase + (size_t)cc * G + g];
            num += f * g_pacc[(sbase + (size_t)cc * G + g) * D + d];
        }
        out[((size_t)q0 * HQ + h * G + g) * D + d] = num / (L + 1e-10f);
    }

    if (tid == 0) g_cnt[s * HKV + h] = 0;   // reset for next graph replay
}

extern "C" void kernel_launch(void* const* d_in, const int* in_sizes, int n_in,
                              void* d_out, int out_size) {
    const float* q      = (const float*)d_in[0];
    const float* kc     = (const float*)d_in[1];
    const float* vc     = (const float*)d_in[2];
    const int*   bt     = (const int*)d_in[3];
    const int*   sl     = (const int*)d_in[4];
    const float* slopes = (const float*)d_in[5];
    const int*   qsl    = (const int*)d_in[6];
    float* out = (float*)d_out;

    const int S = in_sizes[4];

    dim3 grid(HKV, S, MAXCH);
    paged_attn_split_kernel<<<grid, THREADS>>>(q, kc, vc, bt, sl, slopes, qsl, out);
}